// round 9
// baseline (speedup 1.0000x reference)
#include <cuda_runtime.h>
#include <cuda_fp16.h>
#include <cstdint>

#define VQ_D      64
#define VQ_K      512
#define VQ_N      262144
#define TILE_M    256
#define TPB       256
#define MAIN_GRID (VQ_N / TILE_M)     // 1024
#define VQ_THRESH 2e-3f

// smem layout (bytes)
#define SM_CK   0          // 512 f32 = 2048
#define SM_IDX  2048       // 256 int = 1024
#define SM_RED  3072       // 8 f32
#define SM_AB   4096       // A: hi @0 (32KB), lo @32768 (32KB); then B: hi @0 (64KB), lo @65536 (64KB)
#define SM_TOTAL (4096 + 131072)

// ---- static device buffers ----
__device__ float   vq_ET [VQ_K * VQ_D];
__device__ __half  vq_Ehi[VQ_K * VQ_D];
__device__ __half  vq_Elo[VQ_K * VQ_D];
__device__ float   vq_Ck [VQ_K];
__device__ unsigned vq_flags[VQ_N];
__device__ double  vq_partials[MAIN_GRID];
__device__ double  vq_delta = 0.0;

// ---- helpers ----
__device__ __forceinline__ uint32_t smem_u32(const void* p) {
    uint32_t a;
    asm("{ .reg .u64 t; cvta.to.shared.u64 t, %1; cvt.u32.u64 %0, t; }" : "=r"(a) : "l"(p));
    return a;
}
#define SWZ128(off) ((off) ^ (((off) >> 3) & 0x70))

__device__ __forceinline__ void ldsm4(uint32_t r[4], uint32_t addr) {
    asm volatile("ldmatrix.sync.aligned.m8n8.x4.shared.b16 {%0,%1,%2,%3}, [%4];"
                 : "=r"(r[0]), "=r"(r[1]), "=r"(r[2]), "=r"(r[3]) : "r"(addr));
}
// NOTE: non-volatile — ptxas may schedule/interleave HMMAs freely (dataflow only)
__device__ __forceinline__ void mma16816(float c[4], const uint32_t a[4], const uint32_t* b) {
    asm("mma.sync.aligned.m16n8k16.row.col.f32.f16.f16.f32 "
        "{%0,%1,%2,%3},{%4,%5,%6,%7},{%8,%9},{%0,%1,%2,%3};"
        : "+f"(c[0]), "+f"(c[1]), "+f"(c[2]), "+f"(c[3])
        : "r"(a[0]), "r"(a[1]), "r"(a[2]), "r"(a[3]), "r"(b[0]), "r"(b[1]));
}

// ---- prologue: E^T, fp16 split, norms ----
__global__ void vq_prologue(const float* __restrict__ emb) {
    int k = threadIdx.x;
    if (k >= VQ_K) return;
    float ss = 0.f;
    for (int d = 0; d < VQ_D; d++) {
        float v = emb[d * VQ_K + k];
        vq_ET[k * VQ_D + d] = v;
        __half h = __float2half_rn(v);
        __half l = __float2half_rn(v - __half2float(h));
        vq_Ehi[k * VQ_D + d] = h;
        vq_Elo[k * VQ_D + d] = l;
        ss = fmaf(v, v, ss);
    }
    vq_Ck[k] = ss;
}

// ---- main: HMMA 3-pass distance GEMM + argmin ----
__global__ void __launch_bounds__(TPB, 1)
vq_main(const float* __restrict__ x, float* __restrict__ out)
{
    extern __shared__ char smem[];
    uint32_t sb = smem_u32(smem);
    int tid = threadIdx.x, wid = tid >> 5, lid = tid & 31;
    int wbase = wid * 32;
    float* CkS = (float*)(smem + SM_CK);

    for (int k = tid; k < VQ_K; k += TPB) CkS[k] = vq_Ck[k];

    // stage A (x tile 256x64 f32 -> fp16 hi/lo, SW128, 128B rows)
    const float4* xt = reinterpret_cast<const float4*>(x + (size_t)blockIdx.x * TILE_M * VQ_D);
    #pragma unroll
    for (int i = 0; i < 16; i++) {
        int u = tid + TPB * i;                 // 4096 float4s
        int r = u >> 4, c = u & 15;
        float4 v = xt[u];
        __half h0 = __float2half_rn(v.x), h1 = __float2half_rn(v.y);
        __half h2 = __float2half_rn(v.z), h3 = __float2half_rn(v.w);
        __half l0 = __float2half_rn(v.x - __half2float(h0));
        __half l1 = __float2half_rn(v.y - __half2float(h1));
        __half l2 = __float2half_rn(v.z - __half2float(h2));
        __half l3 = __float2half_rn(v.w - __half2float(h3));
        uint32_t off = SWZ128((uint32_t)(r * 128 + c * 8));
        *(__half2*)(smem + SM_AB +         off)     = __halves2half2(h0, h1);
        *(__half2*)(smem + SM_AB +         off + 4) = __halves2half2(h2, h3);
        *(__half2*)(smem + SM_AB + 32768 + off)     = __halves2half2(l0, l1);
        *(__half2*)(smem + SM_AB + 32768 + off + 4) = __halves2half2(l2, l3);
    }
    __syncthreads();

    // load A fragments to regs (warp owns rows wbase..wbase+31)
    uint32_t ahi[2][4][4], alo[2][4][4];
    {
        int rL = (lid & 15);
        int kL = (lid >> 4) * 16;
        #pragma unroll
        for (int mt = 0; mt < 2; mt++)
            #pragma unroll
            for (int ks = 0; ks < 4; ks++) {
                uint32_t boff = (uint32_t)((wbase + mt * 16 + rL) * 128 + ks * 32 + kL);
                ldsm4(ahi[mt][ks], sb + SM_AB +         SWZ128(boff));
                ldsm4(alo[mt][ks], sb + SM_AB + 32768 + SWZ128(boff));
            }
    }
    __syncthreads();

    // stage B (codebook 512x64 fp16 hi/lo, overlays A region)
    const ulonglong2* Gh = reinterpret_cast<const ulonglong2*>(vq_Ehi);
    const ulonglong2* Gl = reinterpret_cast<const ulonglong2*>(vq_Elo);
    #pragma unroll
    for (int i = 0; i < 16; i++) {
        int u = tid + TPB * i;                 // 4096 16B-chunks
        int code = u >> 3, c8 = u & 7;
        uint32_t off = SWZ128((uint32_t)(code * 128 + c8 * 16));
        *(ulonglong2*)(smem + SM_AB +         off) = Gh[u];
        *(ulonglong2*)(smem + SM_AB + 65536 + off) = Gl[u];
    }
    __syncthreads();

    // mainloop
    float minv[4], min2[4]; int mink[4];
    #pragma unroll
    for (int s = 0; s < 4; s++) { minv[s] = 3.4e38f; min2[s] = 3.4e38f; mink[s] = 0; }
    int qcol = (lid & 3) * 2;
    int cL = (lid & 7) + ((lid >> 4) ? 8 : 0);     // B ldmatrix code-lane offset
    int kL2 = ((lid >> 3) & 1) * 16;               // B ldmatrix k-byte offset

    #pragma unroll 1
    for (int chunk = 0; chunk < 8; chunk++) {
        int n0 = chunk * 64;
        float acc[2][8][4];
        #pragma unroll
        for (int a = 0; a < 2; a++)
            #pragma unroll
            for (int b = 0; b < 8; b++)
                #pragma unroll
                for (int c = 0; c < 4; c++) acc[a][b][c] = 0.f;

        #pragma unroll
        for (int ks = 0; ks < 4; ks++) {
            uint32_t bh[4][4], bl[4][4];
            #pragma unroll
            for (int p = 0; p < 4; p++) {
                uint32_t boff = (uint32_t)((n0 + p * 16 + cL) * 128 + ks * 32 + kL2);
                ldsm4(bh[p], sb + SM_AB +         SWZ128(boff));
                ldsm4(bl[p], sb + SM_AB + 65536 + SWZ128(boff));
            }
            // pass-OUTERMOST: 16 independent MMAs between same-acc reuses,
            // so the RAW dependency (acc chains) is fully latency-hidden.
            #pragma unroll
            for (int pass = 0; pass < 3; pass++) {
                #pragma unroll
                for (int mt = 0; mt < 2; mt++) {
                    const uint32_t* afrag = (pass == 2) ? alo[mt][ks] : ahi[mt][ks];
                    #pragma unroll
                    for (int p = 0; p < 4; p++)
                        #pragma unroll
                        for (int t2 = 0; t2 < 2; t2++) {
                            const uint32_t* bfrag = (pass == 1) ? &bl[p][t2 * 2]
                                                                : &bh[p][t2 * 2];
                            mma16816(acc[mt][2 * p + t2], afrag, bfrag);
                        }
                }
            }
        }
        // distances + min/min2 update
        #pragma unroll
        for (int nt = 0; nt < 8; nt++) {
            int k0 = n0 + nt * 8 + qcol;
            float ck0 = CkS[k0], ck1 = CkS[k0 + 1];
            #pragma unroll
            for (int mt = 0; mt < 2; mt++)
                #pragma unroll
                for (int h = 0; h < 2; h++) {
                    int s = mt * 2 + h;
                    float d0 = fmaf(-2.f, acc[mt][nt][h * 2],     ck0);
                    float d1 = fmaf(-2.f, acc[mt][nt][h * 2 + 1], ck1);
                    if (d0 < minv[s]) { min2[s] = minv[s]; minv[s] = d0; mink[s] = k0; }
                    else if (d0 < min2[s]) min2[s] = d0;
                    if (d1 < minv[s]) { min2[s] = minv[s]; minv[s] = d1; mink[s] = k0 + 1; }
                    else if (d1 < min2[s]) min2[s] = d1;
                }
        }
    }

    // quad reduce (lanes differing in bits 0-1 cover different columns)
    #pragma unroll
    for (int off = 1; off <= 2; off <<= 1) {
        #pragma unroll
        for (int s = 0; s < 4; s++) {
            float ov = __shfl_xor_sync(0xffffffffu, minv[s], off);
            float o2 = __shfl_xor_sync(0xffffffffu, min2[s], off);
            int   ok = __shfl_xor_sync(0xffffffffu, mink[s], off);
            if (ov < minv[s] || (ov == minv[s] && ok < mink[s])) {
                min2[s] = fminf(minv[s], o2);
                minv[s] = ov; mink[s] = ok;
            } else {
                min2[s] = fminf(min2[s], ov);
            }
        }
    }
    if ((lid & 3) == 0) {
        int qr = lid >> 2;
        #pragma unroll
        for (int s = 0; s < 4; s++) {
            int row = wbase + (s >> 1) * 16 + (s & 1) * 8 + qr;
            ((int*)(smem + SM_IDX))[row] = mink[s];
            long long n = (long long)blockIdx.x * TILE_M + row;
            vq_flags[n] = (min2[s] - minv[s] < VQ_THRESH) ? (unsigned)mink[s] : 0xffffffffu;
        }
    }
    __syncthreads();

    // epilogue: one row per thread — gather exact code, write, loss
    {
        int row = tid;
        long long n = (long long)blockIdx.x * TILE_M + row;
        int mk = ((int*)(smem + SM_IDX))[row];
        const float4* q4 = reinterpret_cast<const float4*>(vq_ET + mk * VQ_D);
        const float4* x4 = reinterpret_cast<const float4*>(x + n * VQ_D);
        float4* o4 = reinterpret_cast<float4*>(out + n * VQ_D);
        float ls = 0.f;
        #pragma unroll
        for (int i = 0; i < 16; i++) {
            float4 q = q4[i], xv = x4[i];
            o4[i] = q;
            float e0 = q.x - xv.x, e1 = q.y - xv.y, e2 = q.z - xv.z, e3 = q.w - xv.w;
            ls = fmaf(e0, e0, ls); ls = fmaf(e1, e1, ls);
            ls = fmaf(e2, e2, ls); ls = fmaf(e3, e3, ls);
        }
        #pragma unroll
        for (int o = 16; o; o >>= 1) ls += __shfl_xor_sync(0xffffffffu, ls, o);
        if (lid == 0) ((float*)(smem + SM_RED))[wid] = ls;
    }
    __syncthreads();
    if (tid == 0) {
        float s = 0.f;
        #pragma unroll
        for (int w = 0; w < 8; w++) s += ((float*)(smem + SM_RED))[w];
        vq_partials[blockIdx.x] = (double)s;
    }
}

// ---- fixup: exact re-argmin for flagged rows (round-1-matching arithmetic) ----
__global__ void vq_fixup(const float* __restrict__ x, float* __restrict__ out)
{
    int gw = (blockIdx.x * blockDim.x + threadIdx.x) >> 5;
    int lid = threadIdx.x & 31;
    long long base = (long long)gw * 32;
    if (base >= VQ_N) return;

    unsigned my = vq_flags[base + lid];
    unsigned mask = __ballot_sync(0xffffffffu, my != 0xffffffffu);
    while (mask) {
        int src = __ffs(mask) - 1;
        mask &= mask - 1;
        long long row = base + src;
        unsigned oldidx = __shfl_sync(0xffffffffu, my, src);

        float4 xr[16];
        const float4* x4 = reinterpret_cast<const float4*>(x + row * VQ_D);
        #pragma unroll
        for (int i = 0; i < 16; i++) xr[i] = x4[i];

        float bestd = 3.4e38f; int bestk = 0x7fffffff;
        for (int j = 0; j < 16; j++) {
            int k = lid + 32 * j;
            const float4* e4 = reinterpret_cast<const float4*>(vq_ET + k * VQ_D);
            float accE = 0.f, accO = 0.f;     // even/odd-dim chains (round-1 order)
            #pragma unroll
            for (int i = 0; i < 16; i++) {
                float4 e = e4[i];
                accE = fmaf(xr[i].x, e.x, accE);
                accO = fmaf(xr[i].y, e.y, accO);
                accE = fmaf(xr[i].z, e.z, accE);
                accO = fmaf(xr[i].w, e.w, accO);
            }
            float d = fmaf(-2.f, accE + accO, vq_Ck[k]);
            if (d < bestd || (d == bestd && k < bestk)) { bestd = d; bestk = k; }
        }
        #pragma unroll
        for (int o = 16; o; o >>= 1) {
            float od = __shfl_xor_sync(0xffffffffu, bestd, o);
            int   ok = __shfl_xor_sync(0xffffffffu, bestk, o);
            if (od < bestd || (od == bestd && ok < bestk)) { bestd = od; bestk = ok; }
        }
        unsigned newidx = (unsigned)bestk;

        if (newidx != oldidx) {
            int d0 = lid * 2, d1 = lid * 2 + 1;
            float xv0 = x[row * VQ_D + d0], xv1 = x[row * VQ_D + d1];
            float qo0 = out[row * VQ_D + d0], qo1 = out[row * VQ_D + d1];
            float qn0 = vq_ET[newidx * VQ_D + d0], qn1 = vq_ET[newidx * VQ_D + d1];
            float so = (qo0 - xv0) * (qo0 - xv0) + (qo1 - xv1) * (qo1 - xv1);
            float sn = (qn0 - xv0) * (qn0 - xv0) + (qn1 - xv1) * (qn1 - xv1);
            float dl = sn - so;
            #pragma unroll
            for (int o = 16; o; o >>= 1) dl += __shfl_xor_sync(0xffffffffu, dl, o);
            __syncwarp();
            if (lid < 16)
                reinterpret_cast<float4*>(out + row * VQ_D)[lid] =
                    reinterpret_cast<const float4*>(vq_ET + newidx * VQ_D)[lid];
            if (lid == 0) atomicAdd(&vq_delta, (double)dl);
        }
    }
}

// ---- final: loss scalar ----
__global__ void vq_final(float* out, long long NE)
{
    __shared__ double dred[8];
    double s = 0.0;
    for (int b = threadIdx.x; b < MAIN_GRID; b += 256) s += vq_partials[b];
    #pragma unroll
    for (int o = 16; o; o >>= 1) s += __shfl_xor_sync(0xffffffffu, s, o);
    if ((threadIdx.x & 31) == 0) dred[threadIdx.x >> 5] = s;
    __syncthreads();
    if (threadIdx.x == 0) {
        double tot = vq_delta;
        #pragma unroll
        for (int w = 0; w < 8; w++) tot += dred[w];
        out[NE] = (float)(1.25 * tot / (double)NE);
        vq_delta = 0.0;     // reset for graph replay
    }
}

extern "C" void kernel_launch(void* const* d_in, const int* in_sizes, int n_in,
                              void* d_out, int out_size)
{
    const float* x   = (const float*)d_in[0];
    const float* emb = (const float*)d_in[1];
    float* out = (float*)d_out;
    long long NE = (long long)in_sizes[0];   // 16777216

    cudaFuncSetAttribute(vq_main, cudaFuncAttributeMaxDynamicSharedMemorySize, SM_TOTAL);

    vq_prologue<<<1, 512>>>(emb);
    vq_main<<<MAIN_GRID, TPB, SM_TOTAL>>>(x, out);
    vq_fixup<<<1024, 256>>>(x, out);
    vq_final<<<1, 256>>>(out, NE);
}

// round 10
// speedup vs baseline: 1.4264x; 1.4264x over previous
#include <cuda_runtime.h>
#include <cuda_fp16.h>
#include <cstdint>

#define VQ_D      64
#define VQ_K      512
#define VQ_N      262144
#define TILE_M    256
#define TPB       256
#define MAIN_GRID (VQ_N / TILE_M)     // 1024
#define VQ_THRESH 0.06f               // ~8 sigma of 1-pass hi*hi distance error

// main kernel smem (bytes)
#define SM_CK   0          // 512 f32
#define SM_IDX  2048       // 256 int
#define SM_RED  3072       // 8 f32
#define SM_A    4096       // x-hi tile 256x64 fp16 SW128 (32KB)
#define SM_B    36864      // codebook-hi 512x64 fp16 SW128 (64KB)
#define SM_TOTAL 102400    // 100KB -> 2 CTAs/SM

// fixup kernel smem
#define FX_ES_STRIDE 65    // stride 65 words: bank = (lid + d) % 32, conflict-free
#define FX_CK_OFF    (VQ_K * FX_ES_STRIDE * 4)          // 133120
#define FX_SMEM      (FX_CK_OFF + VQ_K * 4)             // 135168
#define FX_GRID      148
#define FX_WARPS     (FX_GRID * (TPB / 32))             // 1184

// ---- static device buffers ----
__device__ float    vq_ET [VQ_K * VQ_D];
__device__ __half   vq_Ehi[VQ_K * VQ_D];
__device__ float    vq_Ck [VQ_K];
__device__ unsigned vq_list[VQ_N];       // packed (row<<9)|k
__device__ unsigned vq_count;
__device__ double   vq_partials[MAIN_GRID];
__device__ double   vq_delta = 0.0;

// ---- helpers ----
__device__ __forceinline__ uint32_t smem_u32(const void* p) {
    uint32_t a;
    asm("{ .reg .u64 t; cvta.to.shared.u64 t, %1; cvt.u32.u64 %0, t; }" : "=r"(a) : "l"(p));
    return a;
}
#define SWZ128(off) ((off) ^ (((off) >> 3) & 0x70))

__device__ __forceinline__ void ldsm4(uint32_t r[4], uint32_t addr) {
    asm volatile("ldmatrix.sync.aligned.m8n8.x4.shared.b16 {%0,%1,%2,%3}, [%4];"
                 : "=r"(r[0]), "=r"(r[1]), "=r"(r[2]), "=r"(r[3]) : "r"(addr));
}
__device__ __forceinline__ void mma16816(float c[4], const uint32_t a[4], const uint32_t* b) {
    asm("mma.sync.aligned.m16n8k16.row.col.f32.f16.f16.f32 "
        "{%0,%1,%2,%3},{%4,%5,%6,%7},{%8,%9},{%0,%1,%2,%3};"
        : "+f"(c[0]), "+f"(c[1]), "+f"(c[2]), "+f"(c[3])
        : "r"(a[0]), "r"(a[1]), "r"(a[2]), "r"(a[3]), "r"(b[0]), "r"(b[1]));
}

// ---- prologue: E^T, fp16-hi, norms; reset worklist counter (each replay) ----
__global__ void vq_prologue(const float* __restrict__ emb) {
    int k = threadIdx.x;
    if (k == 0) vq_count = 0;
    if (k >= VQ_K) return;
    float ss = 0.f;
    for (int d = 0; d < VQ_D; d++) {
        float v = emb[d * VQ_K + k];
        vq_ET[k * VQ_D + d] = v;
        vq_Ehi[k * VQ_D + d] = __float2half_rn(v);
        ss = fmaf(v, v, ss);
    }
    vq_Ck[k] = ss;
}

// ---- main: 1-pass HMMA distance GEMM + guarded argmin ----
__global__ void __launch_bounds__(TPB, 2)
vq_main(const float* __restrict__ x, float* __restrict__ out)
{
    extern __shared__ char smem[];
    uint32_t sb = smem_u32(smem);
    int tid = threadIdx.x, wid = tid >> 5, lid = tid & 31;
    int wbase = wid * 32;
    float* CkS = (float*)(smem + SM_CK);

    for (int k = tid; k < VQ_K; k += TPB) CkS[k] = vq_Ck[k];

    // stage A-hi (x tile 256x64 -> fp16, SW128 128B rows)
    const float4* xt = reinterpret_cast<const float4*>(x + (size_t)blockIdx.x * TILE_M * VQ_D);
    #pragma unroll
    for (int i = 0; i < 16; i++) {
        int u = tid + TPB * i;
        int r = u >> 4, c = u & 15;
        float4 v = xt[u];
        uint32_t off = SWZ128((uint32_t)(r * 128 + c * 8));
        *(__half2*)(smem + SM_A + off)     = __halves2half2(__float2half_rn(v.x), __float2half_rn(v.y));
        *(__half2*)(smem + SM_A + off + 4) = __halves2half2(__float2half_rn(v.z), __float2half_rn(v.w));
    }
    // stage B-hi (512x64 fp16, 16B chunks coalesced)
    const ulonglong2* Gh = reinterpret_cast<const ulonglong2*>(vq_Ehi);
    #pragma unroll
    for (int i = 0; i < 16; i++) {
        int u = tid + TPB * i;                 // 4096 chunks
        int code = u >> 3, c8 = u & 7;
        uint32_t off = SWZ128((uint32_t)(code * 128 + c8 * 16));
        *(ulonglong2*)(smem + SM_B + off) = Gh[u];
    }
    __syncthreads();

    // A fragments (warp owns rows wbase..wbase+31)
    uint32_t ahi[2][4][4];
    {
        int rL = (lid & 15);
        int kL = (lid >> 4) * 16;
        #pragma unroll
        for (int mt = 0; mt < 2; mt++)
            #pragma unroll
            for (int ks = 0; ks < 4; ks++) {
                uint32_t boff = (uint32_t)((wbase + mt * 16 + rL) * 128 + ks * 32 + kL);
                ldsm4(ahi[mt][ks], sb + SM_A + SWZ128(boff));
            }
    }

    float minv[4], min2[4]; int mink[4];
    #pragma unroll
    for (int s = 0; s < 4; s++) { minv[s] = 3.4e38f; min2[s] = 3.4e38f; mink[s] = 0; }
    int qcol = (lid & 3) * 2;
    int cL = (lid & 7) + ((lid >> 4) ? 8 : 0);
    int kL2 = ((lid >> 3) & 1) * 16;

    #pragma unroll 1
    for (int chunk = 0; chunk < 16; chunk++) {       // 32 codes per chunk
        int n0 = chunk * 32;
        float acc[2][4][4];
        #pragma unroll
        for (int a = 0; a < 2; a++)
            #pragma unroll
            for (int b = 0; b < 4; b++)
                #pragma unroll
                for (int c = 0; c < 4; c++) acc[a][b][c] = 0.f;

        #pragma unroll
        for (int ks = 0; ks < 4; ks++) {
            uint32_t bh[2][4];
            #pragma unroll
            for (int p = 0; p < 2; p++) {
                uint32_t boff = (uint32_t)((n0 + p * 16 + cL) * 128 + ks * 32 + kL2);
                ldsm4(bh[p], sb + SM_B + SWZ128(boff));
            }
            #pragma unroll
            for (int mt = 0; mt < 2; mt++)
                #pragma unroll
                for (int p = 0; p < 2; p++)
                    #pragma unroll
                    for (int t2 = 0; t2 < 2; t2++)
                        mma16816(acc[mt][2 * p + t2], ahi[mt][ks], &bh[p][t2 * 2]);
        }
        #pragma unroll
        for (int nt = 0; nt < 4; nt++) {
            int k0 = n0 + nt * 8 + qcol;
            float ck0 = CkS[k0], ck1 = CkS[k0 + 1];
            #pragma unroll
            for (int mt = 0; mt < 2; mt++)
                #pragma unroll
                for (int h = 0; h < 2; h++) {
                    int s = mt * 2 + h;
                    float d0 = fmaf(-2.f, acc[mt][nt][h * 2],     ck0);
                    float d1 = fmaf(-2.f, acc[mt][nt][h * 2 + 1], ck1);
                    if (d0 < minv[s]) { min2[s] = minv[s]; minv[s] = d0; mink[s] = k0; }
                    else if (d0 < min2[s]) min2[s] = d0;
                    if (d1 < minv[s]) { min2[s] = minv[s]; minv[s] = d1; mink[s] = k0 + 1; }
                    else if (d1 < min2[s]) min2[s] = d1;
                }
        }
    }

    // quad reduce
    #pragma unroll
    for (int off = 1; off <= 2; off <<= 1) {
        #pragma unroll
        for (int s = 0; s < 4; s++) {
            float ov = __shfl_xor_sync(0xffffffffu, minv[s], off);
            float o2 = __shfl_xor_sync(0xffffffffu, min2[s], off);
            int   ok = __shfl_xor_sync(0xffffffffu, mink[s], off);
            if (ov < minv[s] || (ov == minv[s] && ok < mink[s])) {
                min2[s] = fminf(minv[s], o2);
                minv[s] = ov; mink[s] = ok;
            } else {
                min2[s] = fminf(min2[s], ov);
            }
        }
    }
    if ((lid & 3) == 0) {
        int qr = lid >> 2;
        #pragma unroll
        for (int s = 0; s < 4; s++) {
            int row = wbase + (s >> 1) * 16 + (s & 1) * 8 + qr;
            ((int*)(smem + SM_IDX))[row] = mink[s];
            if (min2[s] - minv[s] < VQ_THRESH) {
                unsigned n = (unsigned)(blockIdx.x * TILE_M + row);
                unsigned slot = atomicAdd(&vq_count, 1u);
                vq_list[slot] = (n << 9) | (unsigned)mink[s];
            }
        }
    }
    __syncthreads();

    // epilogue: one row per thread — exact f32 gather, write, loss
    {
        int row = tid;
        long long n = (long long)blockIdx.x * TILE_M + row;
        int mk = ((int*)(smem + SM_IDX))[row];
        const float4* q4 = reinterpret_cast<const float4*>(vq_ET + mk * VQ_D);
        const float4* x4 = reinterpret_cast<const float4*>(x + n * VQ_D);
        float4* o4 = reinterpret_cast<float4*>(out + n * VQ_D);
        float ls = 0.f;
        #pragma unroll
        for (int i = 0; i < 16; i++) {
            float4 q = q4[i], xv = x4[i];
            o4[i] = q;
            float e0 = q.x - xv.x, e1 = q.y - xv.y, e2 = q.z - xv.z, e3 = q.w - xv.w;
            ls = fmaf(e0, e0, ls); ls = fmaf(e1, e1, ls);
            ls = fmaf(e2, e2, ls); ls = fmaf(e3, e3, ls);
        }
        #pragma unroll
        for (int o = 16; o; o >>= 1) ls += __shfl_xor_sync(0xffffffffu, ls, o);
        if (lid == 0) ((float*)(smem + SM_RED))[wid] = ls;
    }
    __syncthreads();
    if (tid == 0) {
        float s = 0.f;
        #pragma unroll
        for (int w = 0; w < 8; w++) s += ((float*)(smem + SM_RED))[w];
        vq_partials[blockIdx.x] = (double)s;
    }
}

// ---- fixup: smem-codebook exact re-argmin over the compacted worklist.
//      Arithmetic replicates the round-1-proven even/odd fma chain order. ----
__global__ void __launch_bounds__(TPB, 1)
vq_fixup(const float* __restrict__ x, float* __restrict__ out)
{
    extern __shared__ char smem[];
    float* Es  = (float*)smem;                     // [512][65]
    float* CkS = (float*)(smem + FX_CK_OFF);       // [512]
    int tid = threadIdx.x, wid = tid >> 5, lid = tid & 31;

    for (int u = tid; u < VQ_K * VQ_D; u += TPB) {
        int k = u >> 6, d = u & 63;
        Es[k * FX_ES_STRIDE + d] = vq_ET[u];
    }
    for (int k = tid; k < VQ_K; k += TPB) CkS[k] = vq_Ck[k];
    __syncthreads();

    unsigned cnt = vq_count;
    int gwarp = blockIdx.x * (TPB / 32) + wid;

    for (unsigned i = gwarp; i < cnt; i += FX_WARPS) {
        unsigned item = vq_list[i];
        long long row = (long long)(item >> 9);
        unsigned oldk = item & 511u;

        // broadcast-load x row
        float4 xr[16];
        const float4* x4 = reinterpret_cast<const float4*>(x + row * VQ_D);
        #pragma unroll
        for (int j = 0; j < 16; j++) xr[j] = x4[j];

        // each lane: 16 codes, exact fp32 even/odd chains
        float bestd = 3.4e38f; int bestk = 0x7fffffff;
        #pragma unroll 1
        for (int j = 0; j < 16; j++) {
            int k = lid + 32 * j;
            const float* er = &Es[k * FX_ES_STRIDE];
            float accE = 0.f, accO = 0.f;
            #pragma unroll
            for (int q = 0; q < 16; q++) {
                float e0 = er[4*q], e1 = er[4*q+1], e2 = er[4*q+2], e3 = er[4*q+3];
                accE = fmaf(xr[q].x, e0, accE);
                accO = fmaf(xr[q].y, e1, accO);
                accE = fmaf(xr[q].z, e2, accE);
                accO = fmaf(xr[q].w, e3, accO);
            }
            float d = fmaf(-2.f, accE + accO, CkS[k]);
            if (d < bestd || (d == bestd && k < bestk)) { bestd = d; bestk = k; }
        }
        #pragma unroll
        for (int o = 16; o; o >>= 1) {
            float od = __shfl_xor_sync(0xffffffffu, bestd, o);
            int   ok = __shfl_xor_sync(0xffffffffu, bestk, o);
            if (od < bestd || (od == bestd && ok < bestk)) { bestd = od; bestk = ok; }
        }
        unsigned newk = (unsigned)bestk;

        if (newk != oldk) {
            int d0 = lid * 2, d1 = lid * 2 + 1;
            float xv0 = x[row * VQ_D + d0], xv1 = x[row * VQ_D + d1];
            float qo0 = out[row * VQ_D + d0], qo1 = out[row * VQ_D + d1];
            float qn0 = Es[newk * FX_ES_STRIDE + d0], qn1 = Es[newk * FX_ES_STRIDE + d1];
            float so = (qo0 - xv0) * (qo0 - xv0) + (qo1 - xv1) * (qo1 - xv1);
            float sn = (qn0 - xv0) * (qn0 - xv0) + (qn1 - xv1) * (qn1 - xv1);
            float dl = sn - so;
            #pragma unroll
            for (int o = 16; o; o >>= 1) dl += __shfl_xor_sync(0xffffffffu, dl, o);
            __syncwarp();
            if (lid < 16)
                reinterpret_cast<float4*>(out + row * VQ_D)[lid] =
                    reinterpret_cast<const float4*>(vq_ET + newk * VQ_D)[lid];
            if (lid == 0) atomicAdd(&vq_delta, (double)dl);
        }
    }
}

// ---- final: loss scalar ----
__global__ void vq_final(float* out, long long NE)
{
    __shared__ double dred[8];
    double s = 0.0;
    for (int b = threadIdx.x; b < MAIN_GRID; b += 256) s += vq_partials[b];
    #pragma unroll
    for (int o = 16; o; o >>= 1) s += __shfl_xor_sync(0xffffffffu, s, o);
    if ((threadIdx.x & 31) == 0) dred[threadIdx.x >> 5] = s;
    __syncthreads();
    if (threadIdx.x == 0) {
        double tot = vq_delta;
        #pragma unroll
        for (int w = 0; w < 8; w++) tot += dred[w];
        out[NE] = (float)(1.25 * tot / (double)NE);
        vq_delta = 0.0;
    }
}

extern "C" void kernel_launch(void* const* d_in, const int* in_sizes, int n_in,
                              void* d_out, int out_size)
{
    const float* x   = (const float*)d_in[0];
    const float* emb = (const float*)d_in[1];
    float* out = (float*)d_out;
    long long NE = (long long)in_sizes[0];

    cudaFuncSetAttribute(vq_main,  cudaFuncAttributeMaxDynamicSharedMemorySize, SM_TOTAL);
    cudaFuncSetAttribute(vq_fixup, cudaFuncAttributeMaxDynamicSharedMemorySize, FX_SMEM);

    vq_prologue<<<1, 512>>>(emb);
    vq_main<<<MAIN_GRID, TPB, SM_TOTAL>>>(x, out);
    vq_fixup<<<FX_GRID, TPB, FX_SMEM>>>(x, out);
    vq_final<<<1, 256>>>(out, NE);
}

// round 11
// speedup vs baseline: 1.8527x; 1.2989x over previous
#include <cuda_runtime.h>
#include <cuda_fp16.h>
#include <cstdint>

#define VQ_D      64
#define VQ_K      512
#define VQ_N      262144
#define TILE_M    128
#define TPB       256
#define MAIN_GRID (VQ_N / TILE_M)     // 2048
#define VQ_THRESH 0.12f               // guard: fp16-scan 4sigma + 2x key-embed + margin

// main smem (bytes): CK 2KB | IDX 512B | RED 32B | A 16KB @4096 | B-half 32KB @20480
#define SM_CK    0
#define SM_IDX   2048
#define SM_RED   2560
#define SM_A     4096
#define SM_B     20480
#define SM_TOTAL 53248      // 52KB -> 3-4 CTAs/SM

// fixup smem
#define FX_ES_STRIDE 65
#define FX_CK_OFF    (VQ_K * FX_ES_STRIDE * 4)
#define FX_SMEM      (FX_CK_OFF + VQ_K * 4)
#define FX_GRID      148
#define FX_WARPS     (FX_GRID * (TPB / 32))

// ---- static device buffers ----
__device__ float    vq_ET [VQ_K * VQ_D];
__device__ __half   vq_Ehi[VQ_K * VQ_D];
__device__ float    vq_Ck [VQ_K];
__device__ unsigned vq_list[VQ_N];
__device__ unsigned vq_count;
__device__ double   vq_partials[MAIN_GRID];
__device__ double   vq_delta = 0.0;

// ---- helpers ----
__device__ __forceinline__ uint32_t smem_u32(const void* p) {
    uint32_t a;
    asm("{ .reg .u64 t; cvta.to.shared.u64 t, %1; cvt.u32.u64 %0, t; }" : "=r"(a) : "l"(p));
    return a;
}
#define SWZ128(off) ((off) ^ (((off) >> 3) & 0x70))

__device__ __forceinline__ void ldsm4(uint32_t r[4], uint32_t addr) {
    asm volatile("ldmatrix.sync.aligned.m8n8.x4.shared.b16 {%0,%1,%2,%3}, [%4];"
                 : "=r"(r[0]), "=r"(r[1]), "=r"(r[2]), "=r"(r[3]) : "r"(addr));
}
__device__ __forceinline__ void mma16816(float c[4], const uint32_t a[4], const uint32_t* b) {
    asm("mma.sync.aligned.m16n8k16.row.col.f32.f16.f16.f32 "
        "{%0,%1,%2,%3},{%4,%5,%6,%7},{%8,%9},{%0,%1,%2,%3};"
        : "+f"(c[0]), "+f"(c[1]), "+f"(c[2]), "+f"(c[3])
        : "r"(a[0]), "r"(a[1]), "r"(a[2]), "r"(a[3]), "r"(b[0]), "r"(b[1]));
}
// distance key: clear low 9 mantissa bits, embed code index (dists positive -> order-preserving)
__device__ __forceinline__ float dkey(float d, int k) {
    return __uint_as_float((__float_as_uint(d) & 0xFFFFFE00u) | (unsigned)k);
}

// ---- prologue: E^T, fp16-hi, norms; reset worklist counter ----
__global__ void vq_prologue(const float* __restrict__ emb) {
    int k = blockIdx.x * 32 + threadIdx.x;
    if (k == 0) vq_count = 0;
    if (k >= VQ_K) return;
    float ss = 0.f;
    #pragma unroll 8
    for (int d = 0; d < VQ_D; d++) {
        float v = emb[d * VQ_K + k];
        vq_ET[k * VQ_D + d] = v;
        vq_Ehi[k * VQ_D + d] = __float2half_rn(v);
        ss = fmaf(v, v, ss);
    }
    vq_Ck[k] = ss;
}

// ---- main: 1-pass HMMA + branchless embedded-key argmin ----
__global__ void __launch_bounds__(TPB, 3)
vq_main(const float* __restrict__ x, float* __restrict__ out)
{
    extern __shared__ char smem[];
    uint32_t sb = smem_u32(smem);
    int tid = threadIdx.x, wid = tid >> 5, lid = tid & 31;
    int wbase = wid * 16;                       // warp owns 16 rows
    float* CkS = (float*)(smem + SM_CK);

    for (int k = tid; k < VQ_K; k += TPB) CkS[k] = vq_Ck[k];

    // stage A-hi (x tile 128x64 -> fp16, SW128 128B rows)
    const float4* xt = reinterpret_cast<const float4*>(x + (size_t)blockIdx.x * TILE_M * VQ_D);
    #pragma unroll
    for (int i = 0; i < 8; i++) {
        int u = tid + TPB * i;                  // 2048 float4s
        int r = u >> 4, c = u & 15;
        float4 v = xt[u];
        uint32_t off = SWZ128((uint32_t)(r * 128 + c * 8));
        *(__half2*)(smem + SM_A + off)     = __halves2half2(__float2half_rn(v.x), __float2half_rn(v.y));
        *(__half2*)(smem + SM_A + off + 4) = __halves2half2(__float2half_rn(v.z), __float2half_rn(v.w));
    }
    // stage B half 0 (256 codes x 64 fp16)
    {
        const ulonglong2* Gh = reinterpret_cast<const ulonglong2*>(vq_Ehi);
        #pragma unroll
        for (int i = 0; i < 8; i++) {
            int u = tid + TPB * i;              // 2048 chunks
            int code = u >> 3, c8 = u & 7;
            uint32_t off = SWZ128((uint32_t)(code * 128 + c8 * 16));
            *(ulonglong2*)(smem + SM_B + off) = Gh[u];
        }
    }
    __syncthreads();

    // A fragments (16 rows per warp)
    uint32_t ahi[4][4];
    {
        int rL = (lid & 15);
        int kL = (lid >> 4) * 16;
        #pragma unroll
        for (int ks = 0; ks < 4; ks++) {
            uint32_t boff = (uint32_t)((wbase + rL) * 128 + ks * 32 + kL);
            ldsm4(ahi[ks], sb + SM_A + SWZ128(boff));
        }
    }

    // 4 chains (one per acc slot): embedded-key min / min2
    float minv[4], min2[4];
    #pragma unroll
    for (int v = 0; v < 4; v++) { minv[v] = 3.4e38f; min2[v] = 3.4e38f; }
    int qcol = (lid & 3) * 2;
    int cL = (lid & 7) + ((lid >> 4) ? 8 : 0);
    int kL2 = ((lid >> 3) & 1) * 16;

    #pragma unroll 1
    for (int half = 0; half < 2; half++) {
        if (half) {                              // restage B with second 256 codes
            __syncthreads();
            const ulonglong2* Gh = reinterpret_cast<const ulonglong2*>(vq_Ehi + 256 * VQ_D);
            #pragma unroll
            for (int i = 0; i < 8; i++) {
                int u = tid + TPB * i;
                int code = u >> 3, c8 = u & 7;
                uint32_t off = SWZ128((uint32_t)(code * 128 + c8 * 16));
                *(ulonglong2*)(smem + SM_B + off) = Gh[u];
            }
            __syncthreads();
        }
        int kb0 = half * 256;

        #pragma unroll 1
        for (int chunk = 0; chunk < 8; chunk++) {   // 32 codes per chunk
            int n0 = chunk * 32;
            float acc[4][4];
            #pragma unroll
            for (int b = 0; b < 4; b++)
                #pragma unroll
                for (int c = 0; c < 4; c++) acc[b][c] = 0.f;

            #pragma unroll
            for (int ks = 0; ks < 4; ks++) {
                uint32_t bh[2][4];
                #pragma unroll
                for (int p = 0; p < 2; p++) {
                    uint32_t boff = (uint32_t)((n0 + p * 16 + cL) * 128 + ks * 32 + kL2);
                    ldsm4(bh[p], sb + SM_B + SWZ128(boff));
                }
                #pragma unroll
                for (int p = 0; p < 2; p++)
                    #pragma unroll
                    for (int t2 = 0; t2 < 2; t2++)
                        mma16816(acc[2 * p + t2], ahi[ks], &bh[p][t2 * 2]);
            }
            // branchless scan: d -> key(embed k) -> min/min2 chains
            #pragma unroll
            for (int nt = 0; nt < 4; nt++) {
                int k0 = kb0 + n0 + nt * 8 + qcol;
                float ck0 = CkS[k0], ck1 = CkS[k0 + 1];
                #pragma unroll
                for (int v = 0; v < 4; v++) {
                    float ck = (v & 1) ? ck1 : ck0;
                    int   kk = k0 + (v & 1);
                    float key = dkey(fmaf(-2.f, acc[nt][v], ck), kk);
                    float nmax = fmaxf(minv[v], key);
                    minv[v] = fminf(minv[v], key);
                    min2[v] = fminf(min2[v], nmax);
                }
            }
        }
    }

    // combine col pairs: slots (0,1) -> rowA, (2,3) -> rowB
    float mA  = fminf(minv[0], minv[1]);
    float mA2 = fminf(fmaxf(minv[0], minv[1]), fminf(min2[0], min2[1]));
    float mB  = fminf(minv[2], minv[3]);
    float mB2 = fminf(fmaxf(minv[2], minv[3]), fminf(min2[2], min2[3]));

    // quad reduce (lanes differing in bits 0-1 hold other columns)
    #pragma unroll
    for (int off = 1; off <= 2; off <<= 1) {
        float oA  = __shfl_xor_sync(0xffffffffu, mA,  off);
        float oA2 = __shfl_xor_sync(0xffffffffu, mA2, off);
        float oB  = __shfl_xor_sync(0xffffffffu, mB,  off);
        float oB2 = __shfl_xor_sync(0xffffffffu, mB2, off);
        mA2 = fminf(fmaxf(mA, oA), fminf(mA2, oA2));
        mA  = fminf(mA, oA);
        mB2 = fminf(fmaxf(mB, oB), fminf(mB2, oB2));
        mB  = fminf(mB, oB);
    }
    if ((lid & 3) == 0) {
        int qr = lid >> 2;
        int rowA = wbase + qr, rowB = wbase + 8 + qr;
        int kA = (int)(__float_as_uint(mA) & 511u);
        int kB = (int)(__float_as_uint(mB) & 511u);
        ((int*)(smem + SM_IDX))[rowA] = kA;
        ((int*)(smem + SM_IDX))[rowB] = kB;
        if (mA2 - mA < VQ_THRESH) {
            unsigned n = (unsigned)(blockIdx.x * TILE_M + rowA);
            unsigned slot = atomicAdd(&vq_count, 1u);
            vq_list[slot] = (n << 9) | (unsigned)kA;
        }
        if (mB2 - mB < VQ_THRESH) {
            unsigned n = (unsigned)(blockIdx.x * TILE_M + rowB);
            unsigned slot = atomicAdd(&vq_count, 1u);
            vq_list[slot] = (n << 9) | (unsigned)kB;
        }
    }
    __syncthreads();

    // epilogue: 2 threads per row (8 float4 each) — exact f32 gather + loss
    {
        int row  = tid >> 1;
        int part = (tid & 1) * 8;
        long long n = (long long)blockIdx.x * TILE_M + row;
        int mk = ((int*)(smem + SM_IDX))[row];
        const float4* q4 = reinterpret_cast<const float4*>(vq_ET + mk * VQ_D) + part;
        const float4* x4 = reinterpret_cast<const float4*>(x + n * VQ_D) + part;
        float4* o4 = reinterpret_cast<float4*>(out + n * VQ_D) + part;
        float ls = 0.f;
        #pragma unroll
        for (int i = 0; i < 8; i++) {
            float4 q = q4[i], xv = x4[i];
            o4[i] = q;
            float e0 = q.x - xv.x, e1 = q.y - xv.y, e2 = q.z - xv.z, e3 = q.w - xv.w;
            ls = fmaf(e0, e0, ls); ls = fmaf(e1, e1, ls);
            ls = fmaf(e2, e2, ls); ls = fmaf(e3, e3, ls);
        }
        #pragma unroll
        for (int o = 16; o; o >>= 1) ls += __shfl_xor_sync(0xffffffffu, ls, o);
        if (lid == 0) ((float*)(smem + SM_RED))[wid] = ls;
    }
    __syncthreads();
    if (tid == 0) {
        float s = 0.f;
        #pragma unroll
        for (int w = 0; w < 8; w++) s += ((float*)(smem + SM_RED))[w];
        vq_partials[blockIdx.x] = (double)s;
    }
}

// ---- fixup: smem-codebook exact re-argmin (round-1-proven fma ordering) ----
__global__ void __launch_bounds__(TPB, 1)
vq_fixup(const float* __restrict__ x, float* __restrict__ out)
{
    extern __shared__ char smem[];
    float* Es  = (float*)smem;
    float* CkS = (float*)(smem + FX_CK_OFF);
    int tid = threadIdx.x, wid = tid >> 5, lid = tid & 31;

    for (int u = tid; u < VQ_K * VQ_D; u += TPB) {
        int k = u >> 6, d = u & 63;
        Es[k * FX_ES_STRIDE + d] = vq_ET[u];
    }
    for (int k = tid; k < VQ_K; k += TPB) CkS[k] = vq_Ck[k];
    __syncthreads();

    unsigned cnt = vq_count;
    int gwarp = blockIdx.x * (TPB / 32) + wid;

    for (unsigned i = gwarp; i < cnt; i += FX_WARPS) {
        unsigned item = vq_list[i];
        long long row = (long long)(item >> 9);
        unsigned oldk = item & 511u;

        float4 xr[16];
        const float4* x4 = reinterpret_cast<const float4*>(x + row * VQ_D);
        #pragma unroll
        for (int j = 0; j < 16; j++) xr[j] = x4[j];

        float bestd = 3.4e38f; int bestk = 0x7fffffff;
        #pragma unroll 1
        for (int j = 0; j < 16; j++) {
            int k = lid + 32 * j;
            const float* er = &Es[k * FX_ES_STRIDE];
            float accE = 0.f, accO = 0.f;
            #pragma unroll
            for (int q = 0; q < 16; q++) {
                float e0 = er[4*q], e1 = er[4*q+1], e2 = er[4*q+2], e3 = er[4*q+3];
                accE = fmaf(xr[q].x, e0, accE);
                accO = fmaf(xr[q].y, e1, accO);
                accE = fmaf(xr[q].z, e2, accE);
                accO = fmaf(xr[q].w, e3, accO);
            }
            float d = fmaf(-2.f, accE + accO, CkS[k]);
            if (d < bestd || (d == bestd && k < bestk)) { bestd = d; bestk = k; }
        }
        #pragma unroll
        for (int o = 16; o; o >>= 1) {
            float od = __shfl_xor_sync(0xffffffffu, bestd, o);
            int   ok = __shfl_xor_sync(0xffffffffu, bestk, o);
            if (od < bestd || (od == bestd && ok < bestk)) { bestd = od; bestk = ok; }
        }
        unsigned newk = (unsigned)bestk;

        if (newk != oldk) {
            int d0 = lid * 2, d1 = lid * 2 + 1;
            float xv0 = x[row * VQ_D + d0], xv1 = x[row * VQ_D + d1];
            float qo0 = out[row * VQ_D + d0], qo1 = out[row * VQ_D + d1];
            float qn0 = Es[newk * FX_ES_STRIDE + d0], qn1 = Es[newk * FX_ES_STRIDE + d1];
            float so = (qo0 - xv0) * (qo0 - xv0) + (qo1 - xv1) * (qo1 - xv1);
            float sn = (qn0 - xv0) * (qn0 - xv0) + (qn1 - xv1) * (qn1 - xv1);
            float dl = sn - so;
            #pragma unroll
            for (int o = 16; o; o >>= 1) dl += __shfl_xor_sync(0xffffffffu, dl, o);
            __syncwarp();
            if (lid < 16)
                reinterpret_cast<float4*>(out + row * VQ_D)[lid] =
                    reinterpret_cast<const float4*>(vq_ET + newk * VQ_D)[lid];
            if (lid == 0) atomicAdd(&vq_delta, (double)dl);
        }
    }
}

// ---- final: loss scalar ----
__global__ void vq_final(float* out, long long NE)
{
    __shared__ double dred[8];
    double s = 0.0;
    for (int b = threadIdx.x; b < MAIN_GRID; b += 256) s += vq_partials[b];
    #pragma unroll
    for (int o = 16; o; o >>= 1) s += __shfl_xor_sync(0xffffffffu, s, o);
    if ((threadIdx.x & 31) == 0) dred[threadIdx.x >> 5] = s;
    __syncthreads();
    if (threadIdx.x == 0) {
        double tot = vq_delta;
        #pragma unroll
        for (int w = 0; w < 8; w++) tot += dred[w];
        out[NE] = (float)(1.25 * tot / (double)NE);
        vq_delta = 0.0;
    }
}

extern "C" void kernel_launch(void* const* d_in, const int* in_sizes, int n_in,
                              void* d_out, int out_size)
{
    const float* x   = (const float*)d_in[0];
    const float* emb = (const float*)d_in[1];
    float* out = (float*)d_out;
    long long NE = (long long)in_sizes[0];

    cudaFuncSetAttribute(vq_main,  cudaFuncAttributeMaxDynamicSharedMemorySize, SM_TOTAL);
    cudaFuncSetAttribute(vq_fixup, cudaFuncAttributeMaxDynamicSharedMemorySize, FX_SMEM);

    vq_prologue<<<16, 32>>>(emb);
    vq_main<<<MAIN_GRID, TPB, SM_TOTAL>>>(x, out);
    vq_fixup<<<FX_GRID, TPB, FX_SMEM>>>(x, out);
    vq_final<<<1, 256>>>(out, NE);
}